// round 7
// baseline (speedup 1.0000x reference)
#include <cuda_runtime.h>
#include <cuda_bf16.h>
#include <cstdint>

// ---------------- problem constants ----------------
#define WIN     400
#define HOP     100
#define PADL    300
#define T_IN    480000
#define BATCH   32
#define C_OUT   514
#define F_OUT   4803

#define MROWS   512               // C_OUT minus zero-structure channels 257, 513
#define KREAL   400               // 5 uniform chunks of 80
#define KCH     80
#define NCHUNK  5
#define XPAD    486784

#define TILE_M  128
#define TILE_N  128
#define NT_C    4
#define NT_F    38
#define THREADS 512

// ---------------- device scratch ----------------
__device__ __nv_bfloat16 g_wh[MROWS * KREAL];
__device__ __nv_bfloat16 g_wl[MROWS * KREAL];
__device__ __nv_bfloat16 g_xh[BATCH * (size_t)XPAD];
__device__ __nv_bfloat16 g_xl[BATCH * (size_t)XPAD];

// ---------------- smem layout ----------------
// 80 bf16 = 160B per row + 16B pad -> pitch 176 (mod 128 = 48: conflict-free ldsm)
#define PITCH_B      176
#define SPLIT_BYTES  (128 * PITCH_B)               // 22528
#define STAGE_BYTES  (4 * SPLIT_BYTES)             // Ah, Al, Bh, Bl = 90112
#define OFF_A(s)     ((s) * STAGE_BYTES)
#define OFF_B(s)     ((s) * STAGE_BYTES + 2 * SPLIT_BYTES)
#define SMEM_TOTAL   (2 * STAGE_BYTES)             // 180224
#define EPI_PITCH    129

// ---------------- helpers ----------------
__device__ __forceinline__ uint32_t smem_u32(const void* p) {
    uint32_t a;
    asm("{ .reg .u64 t; cvta.to.shared.u64 t, %1; cvt.u32.u64 %0, t; }" : "=r"(a) : "l"(p));
    return a;
}
__device__ __forceinline__ void cp16(uint32_t dst, const void* src) {
    asm volatile("cp.async.cg.shared.global [%0], [%1], 16;" :: "r"(dst), "l"(src));
}
__device__ __forceinline__ void cp8(uint32_t dst, const void* src) {
    asm volatile("cp.async.ca.shared.global [%0], [%1], 8;" :: "r"(dst), "l"(src));
}
__device__ __forceinline__ void cp_commit() {
    asm volatile("cp.async.commit_group;" ::: "memory");
}
template <int N>
__device__ __forceinline__ void cp_wait() {
    asm volatile("cp.async.wait_group %0;" :: "n"(N) : "memory");
}
__device__ __forceinline__ void ldsm_x4(uint32_t& r0, uint32_t& r1, uint32_t& r2, uint32_t& r3,
                                        uint32_t addr) {
    asm volatile("ldmatrix.sync.aligned.m8n8.x4.shared.b16 {%0,%1,%2,%3}, [%4];"
                 : "=r"(r0), "=r"(r1), "=r"(r2), "=r"(r3) : "r"(addr));
}
__device__ __forceinline__ void mma16816(float* d, const uint32_t* a, const uint32_t* b) {
    asm volatile(
        "mma.sync.aligned.m16n8k16.row.col.f32.bf16.bf16.f32 "
        "{%0,%1,%2,%3}, {%4,%5,%6,%7}, {%8,%9}, {%0,%1,%2,%3};"
        : "+f"(d[0]), "+f"(d[1]), "+f"(d[2]), "+f"(d[3])
        : "r"(a[0]), "r"(a[1]), "r"(a[2]), "r"(a[3]), "r"(b[0]), "r"(b[1]));
}

// ---------------- prep kernels ----------------
// GEMM row r -> output channel c = r + (r >= 257)
__global__ void prep_w_kernel(const float* __restrict__ w) {
    int idx = blockIdx.x * blockDim.x + threadIdx.x;
    if (idx >= MROWS * KREAL) return;
    int r = idx / KREAL;
    int k = idx - r * KREAL;
    int c = r + (r >= 257);
    float v = w[c * KREAL + k];
    __nv_bfloat16 h = __float2bfloat16(v);
    g_wh[idx] = h;
    g_wl[idx] = __float2bfloat16(v - __bfloat162float(h));
}

__global__ void prep_x_kernel(const float* __restrict__ x) {
    size_t idx = (size_t)blockIdx.x * blockDim.x + threadIdx.x;
    if (idx >= (size_t)BATCH * XPAD) return;
    int b = (int)(idx / XPAD);
    int i = (int)(idx - (size_t)b * XPAD);
    int src = i - PADL;
    float v = (src >= 0 && src < T_IN) ? x[(size_t)b * T_IN + src] : 0.0f;
    __nv_bfloat16 h = __float2bfloat16(v);
    g_xh[idx] = h;
    g_xl[idx] = __float2bfloat16(v - __bfloat162float(h));
}

// ---------------- exact scalar conv for channels 257, 513 ----------------
#define ZSEG 13100
__global__ void edge_ch_kernel(const float* __restrict__ x,
                               const float* __restrict__ w,
                               float* __restrict__ out)
{
    extern __shared__ float zs[];
    float* sxs = zs;
    float* sws = zs + ZSEG;
    const int f0 = blockIdx.x * 128;
    const int ch = (blockIdx.y == 0) ? 257 : 513;
    const int b  = blockIdx.z;
    const int tid = threadIdx.x;

    const int base = f0 * HOP - PADL;
    const float* xb = x + (size_t)b * T_IN;
    for (int i = tid; i < ZSEG; i += 128) {
        int gi = base + i;
        sxs[i] = (gi >= 0 && gi < T_IN) ? xb[gi] : 0.0f;
    }
    for (int i = tid; i < WIN; i += 128) sws[i] = w[ch * WIN + i];
    __syncthreads();

    float acc = 0.0f;
    const float* sp = sxs + tid * HOP;
    #pragma unroll 8
    for (int k = 0; k < WIN; k++) acc = fmaf(sp[k], sws[k], acc);

    int f = f0 + tid;
    if (f < F_OUT) out[((size_t)b * C_OUT + ch) * F_OUT + f] = acc;
}

// ---------------- main pipelined HMMA GEMM kernel ----------------
__global__ __launch_bounds__(THREADS, 1)
void conv_stft_hmma_kernel(float* __restrict__ out)
{
    extern __shared__ char smem[];
    const uint32_t sbase = smem_u32(smem);
    const int tid  = threadIdx.x;
    const int wid  = tid >> 5;
    const int lane = tid & 31;

    const int c0 = blockIdx.x * TILE_M;
    const int f0 = blockIdx.y * TILE_N;
    const int b  = blockIdx.z;

    // ---- per-thread staging role, computed once ----
    // threads 0..255: A rows (split = t>>7, row = t&127), 10 cp16 along row
    // threads 256..511: B rows (frames),                  20 cp8  along row
    const int strow  = tid & 127;
    const int stsplit = (tid >> 7) & 1;
    const char* stg_src0;
    uint32_t    stg_dst0;
    if (tid < 256) {
        const char* wbase = stsplit ? reinterpret_cast<const char*>(g_wl)
                                    : reinterpret_cast<const char*>(g_wh);
        stg_src0 = wbase + ((size_t)(c0 + strow)) * (KREAL * 2);
        stg_dst0 = sbase + stsplit * SPLIT_BYTES + strow * PITCH_B;          // + OFF_A(s)
    } else {
        const char* xbase = stsplit ? reinterpret_cast<const char*>(g_xl + (size_t)b * XPAD)
                                    : reinterpret_cast<const char*>(g_xh + (size_t)b * XPAD);
        stg_src0 = xbase + (size_t)(f0 + strow) * (HOP * 2);
        stg_dst0 = sbase + 2 * SPLIT_BYTES + stsplit * SPLIT_BYTES + strow * PITCH_B; // + OFF_A(s)
    }

    auto stage = [&](int kc, int s) {
        const char* src = stg_src0 + kc * 160;
        uint32_t dst = stg_dst0 + s * STAGE_BYTES;
        if (tid < 256) {
            #pragma unroll
            for (int u = 0; u < 10; u++) cp16(dst + u * 16, src + u * 16);
        } else {
            #pragma unroll
            for (int u = 0; u < 20; u++) cp8(dst + u * 8, src + u * 8);
        }
        cp_commit();
    };

    // warp layout: 4 (M) x 4 (N), warp tile 32x32
    const int m0 = (wid >> 2) * 32;
    const int n0 = (wid & 3) * 32;

    float acc[2][4][4];
    #pragma unroll
    for (int i = 0; i < 2; i++)
        #pragma unroll
        for (int j = 0; j < 4; j++)
            #pragma unroll
            for (int q = 0; q < 4; q++) acc[i][j][q] = 0.0f;

    const uint32_t a_off = (m0 + (lane & 15)) * PITCH_B + (lane >> 4) * 16;
    const uint32_t b_off = (n0 + ((lane >> 4) << 3) + (lane & 7)) * PITCH_B + ((lane >> 3) & 1) * 16;

    stage(0, 0);

    for (int kc = 0; kc < NCHUNK; kc++) {
        const int s = kc & 1;
        if (kc < NCHUNK - 1) { stage(kc + 1, s ^ 1); cp_wait<1>(); }
        else                 { cp_wait<0>(); }
        __syncthreads();

        const uint32_t ah_base = sbase + OFF_A(s) + a_off;
        const uint32_t al_base = ah_base + SPLIT_BYTES;
        const uint32_t bh_base = sbase + OFF_B(s) + b_off;
        const uint32_t bl_base = bh_base + SPLIT_BYTES;

        #pragma unroll
        for (int ks = 0; ks < 5; ks++) {
            uint32_t ah[2][4], al[2][4], bh[2][4], bl[2][4];
            #pragma unroll
            for (int mi = 0; mi < 2; mi++) {
                ldsm_x4(ah[mi][0], ah[mi][1], ah[mi][2], ah[mi][3],
                        ah_base + mi * 16 * PITCH_B + ks * 32);
                ldsm_x4(al[mi][0], al[mi][1], al[mi][2], al[mi][3],
                        al_base + mi * 16 * PITCH_B + ks * 32);
            }
            #pragma unroll
            for (int np = 0; np < 2; np++) {
                ldsm_x4(bh[np][0], bh[np][1], bh[np][2], bh[np][3],
                        bh_base + np * 16 * PITCH_B + ks * 32);
                ldsm_x4(bl[np][0], bl[np][1], bl[np][2], bl[np][3],
                        bl_base + np * 16 * PITCH_B + ks * 32);
            }
            #pragma unroll
            for (int mi = 0; mi < 2; mi++)
                #pragma unroll
                for (int ni = 0; ni < 4; ni++) {
                    const uint32_t* bhf = &bh[ni >> 1][(ni & 1) * 2];
                    const uint32_t* blf = &bl[ni >> 1][(ni & 1) * 2];
                    mma16816(acc[mi][ni], ah[mi], bhf);
                    mma16816(acc[mi][ni], ah[mi], blf);
                    mma16816(acc[mi][ni], al[mi], bhf);
                }
        }
        if (kc < NCHUNK - 1) __syncthreads();
    }

    // ---- epilogue: registers -> smem transpose -> coalesced stores ----
    __syncthreads();
    float* epi = reinterpret_cast<float*>(smem);
    const int g = lane >> 2;
    const int t = lane & 3;
    #pragma unroll
    for (int mi = 0; mi < 2; mi++)
        #pragma unroll
        for (int ni = 0; ni < 4; ni++) {
            int col = n0 + ni * 8 + t * 2;
            #pragma unroll
            for (int half = 0; half < 2; half++) {
                int row = m0 + mi * 16 + half * 8 + g;
                epi[row * EPI_PITCH + col]     = acc[mi][ni][half * 2];
                epi[row * EPI_PITCH + col + 1] = acc[mi][ni][half * 2 + 1];
            }
        }
    __syncthreads();

    #pragma unroll 4
    for (int idx = tid; idx < TILE_M * TILE_N; idx += THREADS) {
        int row = idx >> 7;
        int col = idx & 127;
        int R = c0 + row;
        int c = R + (R >= 257);
        int f = f0 + col;
        if (f < F_OUT)
            out[((size_t)b * C_OUT + c) * F_OUT + f] = epi[row * EPI_PITCH + col];
    }
}

// ---------------- launcher ----------------
extern "C" void kernel_launch(void* const* d_in, const int* in_sizes, int n_in,
                              void* d_out, int out_size)
{
    const float* x = (const float*)d_in[0];
    const float* w = (const float*)d_in[1];
    float* out = (float*)d_out;

    prep_w_kernel<<<(MROWS * KREAL + 255) / 256, 256>>>(w);
    prep_x_kernel<<<(int)(((size_t)BATCH * XPAD + 255) / 256), 256>>>(x);

    cudaFuncSetAttribute(edge_ch_kernel,
                         cudaFuncAttributeMaxDynamicSharedMemorySize,
                         (ZSEG + WIN) * (int)sizeof(float));
    dim3 zgrid(NT_F, 2, BATCH);
    edge_ch_kernel<<<zgrid, 128, (ZSEG + WIN) * sizeof(float)>>>(x, w, out);

    cudaFuncSetAttribute(conv_stft_hmma_kernel,
                         cudaFuncAttributeMaxDynamicSharedMemorySize, SMEM_TOTAL);
    dim3 grid(NT_C, NT_F, BATCH);   // 4 x 38 x 32 = 4864 CTAs
    conv_stft_hmma_kernel<<<grid, THREADS, SMEM_TOTAL>>>(out);
}

// round 8
// speedup vs baseline: 1.1311x; 1.1311x over previous
#include <cuda_runtime.h>
#include <cuda_bf16.h>
#include <cstdint>

// ---------------- problem constants ----------------
#define WIN     400
#define HOP     100
#define PADL    300
#define T_IN    480000
#define BATCH   32
#define C_OUT   514
#define F_OUT   4803

#define MROWS   512               // C_OUT minus zero-structure channels 257, 513
#define KREAL   400               // 6 chunks of 64 + 1 chunk of 16
#define NCHUNK  7
#define XPAD    486784

#define TILE_M  128
#define TILE_N  128
#define NT_C    4
#define NT_F    38
#define THREADS 512

// ---------------- device scratch ----------------
__device__ __nv_bfloat16 g_wh[MROWS * KREAL];
__device__ __nv_bfloat16 g_wl[MROWS * KREAL];
__device__ __nv_bfloat16 g_xh[BATCH * (size_t)XPAD];
__device__ __nv_bfloat16 g_xl[BATCH * (size_t)XPAD];

// ---------------- smem layout (3-stage pipeline) ----------------
#define PITCH_B      144                       // 64 bf16 + 16B pad
#define SPLIT_BYTES  (128 * PITCH_B)           // 18432
#define STAGE_BYTES  (4 * SPLIT_BYTES)         // Ah, Al, Bh, Bl = 73728
#define OFF_A(s)     ((s) * STAGE_BYTES)
#define OFF_B(s)     ((s) * STAGE_BYTES + 2 * SPLIT_BYTES)
#define SMEM_TOTAL   (3 * STAGE_BYTES)         // 221184
#define EPI_PITCH    129

// ---------------- helpers ----------------
__device__ __forceinline__ uint32_t smem_u32(const void* p) {
    uint32_t a;
    asm("{ .reg .u64 t; cvta.to.shared.u64 t, %1; cvt.u32.u64 %0, t; }" : "=r"(a) : "l"(p));
    return a;
}
__device__ __forceinline__ void cp16(uint32_t dst, const void* src) {
    asm volatile("cp.async.cg.shared.global [%0], [%1], 16;" :: "r"(dst), "l"(src));
}
__device__ __forceinline__ void cp8(uint32_t dst, const void* src) {
    asm volatile("cp.async.ca.shared.global [%0], [%1], 8;" :: "r"(dst), "l"(src));
}
__device__ __forceinline__ void cp_commit() {
    asm volatile("cp.async.commit_group;" ::: "memory");
}
template <int N>
__device__ __forceinline__ void cp_wait() {
    asm volatile("cp.async.wait_group %0;" :: "n"(N) : "memory");
}
__device__ __forceinline__ void ldsm_x4(uint32_t& r0, uint32_t& r1, uint32_t& r2, uint32_t& r3,
                                        uint32_t addr) {
    asm volatile("ldmatrix.sync.aligned.m8n8.x4.shared.b16 {%0,%1,%2,%3}, [%4];"
                 : "=r"(r0), "=r"(r1), "=r"(r2), "=r"(r3) : "r"(addr));
}
__device__ __forceinline__ void mma16816(float* d, const uint32_t* a, const uint32_t* b) {
    asm volatile(
        "mma.sync.aligned.m16n8k16.row.col.f32.bf16.bf16.f32 "
        "{%0,%1,%2,%3}, {%4,%5,%6,%7}, {%8,%9}, {%0,%1,%2,%3};"
        : "+f"(d[0]), "+f"(d[1]), "+f"(d[2]), "+f"(d[3])
        : "r"(a[0]), "r"(a[1]), "r"(a[2]), "r"(a[3]), "r"(b[0]), "r"(b[1]));
}

// ---------------- prep kernels ----------------
__global__ void prep_w_kernel(const float* __restrict__ w) {
    int idx = blockIdx.x * blockDim.x + threadIdx.x;
    if (idx >= MROWS * KREAL) return;
    int r = idx / KREAL;
    int k = idx - r * KREAL;
    int c = r + (r >= 257);
    float v = w[c * KREAL + k];
    __nv_bfloat16 h = __float2bfloat16(v);
    g_wh[idx] = h;
    g_wl[idx] = __float2bfloat16(v - __bfloat162float(h));
}

__global__ void prep_x_kernel(const float* __restrict__ x) {
    size_t idx = (size_t)blockIdx.x * blockDim.x + threadIdx.x;
    if (idx >= (size_t)BATCH * XPAD) return;
    int b = (int)(idx / XPAD);
    int i = (int)(idx - (size_t)b * XPAD);
    int src = i - PADL;
    float v = (src >= 0 && src < T_IN) ? x[(size_t)b * T_IN + src] : 0.0f;
    __nv_bfloat16 h = __float2bfloat16(v);
    g_xh[idx] = h;
    g_xl[idx] = __float2bfloat16(v - __bfloat162float(h));
}

// ---------------- exact scalar conv for channels 257, 513 ----------------
#define EFRM 256
#define ZSEG ((EFRM - 1) * HOP + WIN)          // 25900 floats
__global__ void edge_ch_kernel(const float* __restrict__ x,
                               const float* __restrict__ w,
                               float* __restrict__ out)
{
    extern __shared__ float zs[];
    float* sxs = zs;
    float* sws = zs + ZSEG;
    const int f0 = blockIdx.x * EFRM;
    const int ch = (blockIdx.y == 0) ? 257 : 513;
    const int b  = blockIdx.z;
    const int tid = threadIdx.x;

    const int base = f0 * HOP - PADL;
    const float* xb = x + (size_t)b * T_IN;
    for (int i = tid; i < ZSEG; i += EFRM) {
        int gi = base + i;
        sxs[i] = (gi >= 0 && gi < T_IN) ? xb[gi] : 0.0f;
    }
    for (int i = tid; i < WIN; i += EFRM) sws[i] = w[ch * WIN + i];
    __syncthreads();

    float acc = 0.0f;
    const float* sp = sxs + tid * HOP;
    #pragma unroll 8
    for (int k = 0; k < WIN; k++) acc = fmaf(sp[k], sws[k], acc);

    int f = f0 + tid;
    if (f < F_OUT) out[((size_t)b * C_OUT + ch) * F_OUT + f] = acc;
}

// ---------------- main 3-stage pipelined HMMA GEMM kernel ----------------
__global__ __launch_bounds__(THREADS, 1)
void conv_stft_hmma_kernel(float* __restrict__ out)
{
    extern __shared__ char smem[];
    const uint32_t sbase = smem_u32(smem);
    const int tid  = threadIdx.x;
    const int wid  = tid >> 5;
    const int lane = tid & 31;

    const int c0 = blockIdx.x * TILE_M;
    const int f0 = blockIdx.y * TILE_N;
    const int b  = blockIdx.z;

    const char* wh_base = reinterpret_cast<const char*>(g_wh) + (size_t)c0 * KREAL * 2;
    const char* wl_base = reinterpret_cast<const char*>(g_wl) + (size_t)c0 * KREAL * 2;
    const char* xh_base = reinterpret_cast<const char*>(g_xh + (size_t)b * XPAD + f0 * HOP);
    const char* xl_base = reinterpret_cast<const char*>(g_xl + (size_t)b * XPAD + f0 * HOP);

    // coalesced staging: i = tid, unit index fastest (contiguous per warp)
    auto stage = [&](int kc, int s) {
        const int last = (kc == 6);
        const int sha = last ? 1 : 3;          // log2(16B units per A row)
        const int na  = 2 * TILE_M << sha;
        #pragma unroll 2
        for (int i = tid; i < na; i += THREADS) {
            int per = TILE_M << sha;
            int split = i >= per;
            int j = i - split * per;
            int r = j >> sha, u = j & ((1 << sha) - 1);
            const char* src = (split ? wl_base : wh_base) + r * (KREAL * 2) + kc * 128 + u * 16;
            cp16(sbase + OFF_A(s) + split * SPLIT_BYTES + r * PITCH_B + u * 16, src);
        }
        const int shb = last ? 2 : 4;          // log2(8B units per B row)
        const int nb  = 2 * TILE_N << shb;
        #pragma unroll 2
        for (int i = tid; i < nb; i += THREADS) {
            int per = TILE_N << shb;
            int split = i >= per;
            int j = i - split * per;
            int f = j >> shb, u = j & ((1 << shb) - 1);
            const char* src = (split ? xl_base : xh_base) + f * (HOP * 2) + kc * 128 + u * 8;
            cp8(sbase + OFF_B(s) + split * SPLIT_BYTES + f * PITCH_B + u * 8, src);
        }
        cp_commit();
    };

    // warp layout: 4 (M) x 4 (N), warp tile 32x32
    const int m0 = (wid >> 2) * 32;
    const int n0 = (wid & 3) * 32;

    float acc[2][4][4];
    #pragma unroll
    for (int i = 0; i < 2; i++)
        #pragma unroll
        for (int j = 0; j < 4; j++)
            #pragma unroll
            for (int q = 0; q < 4; q++) acc[i][j][q] = 0.0f;

    const uint32_t a_off = (m0 + (lane & 15)) * PITCH_B + (lane >> 4) * 16;
    const uint32_t b_off = (n0 + ((lane >> 4) << 3) + (lane & 7)) * PITCH_B + ((lane >> 3) & 1) * 16;

    stage(0, 0);
    stage(1, 1);

    for (int kc = 0; kc < NCHUNK; kc++) {
        const int s = kc % 3;
        if (kc < NCHUNK - 1) cp_wait<1>(); else cp_wait<0>();
        __syncthreads();                        // buf (kc+2)%3 free; stage kc visible
        if (kc + 2 < NCHUNK) stage(kc + 2, (kc + 2) % 3);

        const uint32_t ah_base = sbase + OFF_A(s) + a_off;
        const uint32_t al_base = ah_base + SPLIT_BYTES;
        const uint32_t bh_base = sbase + OFF_B(s) + b_off;
        const uint32_t bl_base = bh_base + SPLIT_BYTES;
        const int nks = (kc == 6) ? 1 : 4;

        #pragma unroll 4
        for (int ks = 0; ks < nks; ks++) {
            uint32_t ah[2][4], al[2][4], bh[2][4], bl[2][4];
            #pragma unroll
            for (int mi = 0; mi < 2; mi++) {
                ldsm_x4(ah[mi][0], ah[mi][1], ah[mi][2], ah[mi][3],
                        ah_base + mi * 16 * PITCH_B + ks * 32);
                ldsm_x4(al[mi][0], al[mi][1], al[mi][2], al[mi][3],
                        al_base + mi * 16 * PITCH_B + ks * 32);
            }
            #pragma unroll
            for (int np = 0; np < 2; np++) {
                ldsm_x4(bh[np][0], bh[np][1], bh[np][2], bh[np][3],
                        bh_base + np * 16 * PITCH_B + ks * 32);
                ldsm_x4(bl[np][0], bl[np][1], bl[np][2], bl[np][3],
                        bl_base + np * 16 * PITCH_B + ks * 32);
            }
            #pragma unroll
            for (int mi = 0; mi < 2; mi++)
                #pragma unroll
                for (int ni = 0; ni < 4; ni++) {
                    const uint32_t* bhf = &bh[ni >> 1][(ni & 1) * 2];
                    const uint32_t* blf = &bl[ni >> 1][(ni & 1) * 2];
                    mma16816(acc[mi][ni], ah[mi], bhf);
                    mma16816(acc[mi][ni], ah[mi], blf);
                    mma16816(acc[mi][ni], al[mi], bhf);
                }
        }
    }

    // ---- epilogue: registers -> smem transpose -> coalesced stores ----
    __syncthreads();
    float* epi = reinterpret_cast<float*>(smem);
    const int g = lane >> 2;
    const int t = lane & 3;
    #pragma unroll
    for (int mi = 0; mi < 2; mi++)
        #pragma unroll
        for (int ni = 0; ni < 4; ni++) {
            int col = n0 + ni * 8 + t * 2;
            #pragma unroll
            for (int half = 0; half < 2; half++) {
                int row = m0 + mi * 16 + half * 8 + g;
                epi[row * EPI_PITCH + col]     = acc[mi][ni][half * 2];
                epi[row * EPI_PITCH + col + 1] = acc[mi][ni][half * 2 + 1];
            }
        }
    __syncthreads();

    #pragma unroll 4
    for (int idx = tid; idx < TILE_M * TILE_N; idx += THREADS) {
        int row = idx >> 7;
        int col = idx & 127;
        int R = c0 + row;
        int c = R + (R >= 257);
        int f = f0 + col;
        if (f < F_OUT)
            out[((size_t)b * C_OUT + c) * F_OUT + f] = epi[row * EPI_PITCH + col];
    }
}

// ---------------- launcher ----------------
extern "C" void kernel_launch(void* const* d_in, const int* in_sizes, int n_in,
                              void* d_out, int out_size)
{
    const float* x = (const float*)d_in[0];
    const float* w = (const float*)d_in[1];
    float* out = (float*)d_out;

    prep_w_kernel<<<(MROWS * KREAL + 255) / 256, 256>>>(w);
    prep_x_kernel<<<(int)(((size_t)BATCH * XPAD + 255) / 256), 256>>>(x);

    cudaFuncSetAttribute(edge_ch_kernel,
                         cudaFuncAttributeMaxDynamicSharedMemorySize,
                         (ZSEG + WIN) * (int)sizeof(float));
    dim3 zgrid((F_OUT + EFRM - 1) / EFRM, 2, BATCH);   // 19 x 2 x 32
    edge_ch_kernel<<<zgrid, EFRM, (ZSEG + WIN) * sizeof(float)>>>(x, w, out);

    cudaFuncSetAttribute(conv_stft_hmma_kernel,
                         cudaFuncAttributeMaxDynamicSharedMemorySize, SMEM_TOTAL);
    dim3 grid(NT_C, NT_F, BATCH);   // 4 x 38 x 32 = 4864 CTAs
    conv_stft_hmma_kernel<<<grid, THREADS, SMEM_TOTAL>>>(out);
}

// round 9
// speedup vs baseline: 1.2587x; 1.1128x over previous
#include <cuda_runtime.h>
#include <cuda_bf16.h>
#include <cstdint>

// ---------------- problem constants ----------------
#define WIN     400
#define HOP     100
#define PADL    300
#define T_IN    480000
#define BATCH   32
#define C_OUT   514
#define F_OUT   4803

#define MROWS   512               // C_OUT minus zero-structure channels 257, 513
#define KREAL   400               // 6 chunks of 64 + 1 chunk of 16
#define NCHUNK  7
#define XPAD    486784

#define TILE_M  128
#define TILE_N  256
#define NT_C    4
#define NT_F    19                // ceil(4803/256)
#define THREADS 512

// ---------------- device scratch ----------------
__device__ __nv_bfloat16 g_wh[MROWS * KREAL];
__device__ __nv_bfloat16 g_wl[MROWS * KREAL];
__device__ __nv_bfloat16 g_xh[BATCH * (size_t)XPAD];
__device__ __nv_bfloat16 g_xl[BATCH * (size_t)XPAD];

// ---------------- smem layout (2-stage double buffer) ----------------
#define PITCH_B      144                       // 64 bf16 + 16B pad
#define A_SPLIT      (TILE_M * PITCH_B)        // 18432
#define B_SPLIT      (TILE_N * PITCH_B)        // 36864
#define STAGE_BYTES  (2 * A_SPLIT + 2 * B_SPLIT)   // 110592
#define OFF_A(s)     ((s) * STAGE_BYTES)
#define OFF_B(s)     ((s) * STAGE_BYTES + 2 * A_SPLIT)
#define SMEM_TOTAL   (2 * STAGE_BYTES)         // 221184
#define EPI_PITCH    257                       // floats

// ---------------- helpers ----------------
__device__ __forceinline__ uint32_t smem_u32(const void* p) {
    uint32_t a;
    asm("{ .reg .u64 t; cvta.to.shared.u64 t, %1; cvt.u32.u64 %0, t; }" : "=r"(a) : "l"(p));
    return a;
}
__device__ __forceinline__ void cp16(uint32_t dst, const void* src) {
    asm volatile("cp.async.cg.shared.global [%0], [%1], 16;" :: "r"(dst), "l"(src));
}
__device__ __forceinline__ void cp8(uint32_t dst, const void* src) {
    asm volatile("cp.async.ca.shared.global [%0], [%1], 8;" :: "r"(dst), "l"(src));
}
__device__ __forceinline__ void cp_commit() {
    asm volatile("cp.async.commit_group;" ::: "memory");
}
template <int N>
__device__ __forceinline__ void cp_wait() {
    asm volatile("cp.async.wait_group %0;" :: "n"(N) : "memory");
}
__device__ __forceinline__ void ldsm_x4(uint32_t& r0, uint32_t& r1, uint32_t& r2, uint32_t& r3,
                                        uint32_t addr) {
    asm volatile("ldmatrix.sync.aligned.m8n8.x4.shared.b16 {%0,%1,%2,%3}, [%4];"
                 : "=r"(r0), "=r"(r1), "=r"(r2), "=r"(r3) : "r"(addr));
}
__device__ __forceinline__ void mma16816(float* d, const uint32_t* a, const uint32_t* b) {
    asm volatile(
        "mma.sync.aligned.m16n8k16.row.col.f32.bf16.bf16.f32 "
        "{%0,%1,%2,%3}, {%4,%5,%6,%7}, {%8,%9}, {%0,%1,%2,%3};"
        : "+f"(d[0]), "+f"(d[1]), "+f"(d[2]), "+f"(d[3])
        : "r"(a[0]), "r"(a[1]), "r"(a[2]), "r"(a[3]), "r"(b[0]), "r"(b[1]));
}

// ---------------- prep kernels ----------------
// GEMM row r -> output channel c = r + (r >= 257)
__global__ void prep_w_kernel(const float* __restrict__ w) {
    int idx = blockIdx.x * blockDim.x + threadIdx.x;
    if (idx >= MROWS * KREAL) return;
    int r = idx / KREAL;
    int k = idx - r * KREAL;
    int c = r + (r >= 257);
    float v = w[c * KREAL + k];
    __nv_bfloat16 h = __float2bfloat16(v);
    g_wh[idx] = h;
    g_wl[idx] = __float2bfloat16(v - __bfloat162float(h));
}

__global__ void prep_x_kernel(const float* __restrict__ x) {
    size_t idx = (size_t)blockIdx.x * blockDim.x + threadIdx.x;
    if (idx >= (size_t)BATCH * XPAD) return;
    int b = (int)(idx / XPAD);
    int i = (int)(idx - (size_t)b * XPAD);
    int src = i - PADL;
    float v = (src >= 0 && src < T_IN) ? x[(size_t)b * T_IN + src] : 0.0f;
    __nv_bfloat16 h = __float2bfloat16(v);
    g_xh[idx] = h;
    g_xl[idx] = __float2bfloat16(v - __bfloat162float(h));
}

// ---------------- exact scalar conv for channels 257, 513 ----------------
#define EFRM 256
#define ZSEG ((EFRM - 1) * HOP + WIN)          // 25900 floats
__global__ void edge_ch_kernel(const float* __restrict__ x,
                               const float* __restrict__ w,
                               float* __restrict__ out)
{
    extern __shared__ float zs[];
    float* sxs = zs;
    float* sws = zs + ZSEG;
    const int f0 = blockIdx.x * EFRM;
    const int ch = (blockIdx.y == 0) ? 257 : 513;
    const int b  = blockIdx.z;
    const int tid = threadIdx.x;

    const int base = f0 * HOP - PADL;
    const float* xb = x + (size_t)b * T_IN;
    for (int i = tid; i < ZSEG; i += EFRM) {
        int gi = base + i;
        sxs[i] = (gi >= 0 && gi < T_IN) ? xb[gi] : 0.0f;
    }
    for (int i = tid; i < WIN; i += EFRM) sws[i] = w[ch * WIN + i];
    __syncthreads();

    float acc = 0.0f;
    const float* sp = sxs + tid * HOP;
    #pragma unroll 8
    for (int k = 0; k < WIN; k++) acc = fmaf(sp[k], sws[k], acc);

    int f = f0 + tid;
    if (f < F_OUT) out[((size_t)b * C_OUT + ch) * F_OUT + f] = acc;
}

// ---------------- main HMMA GEMM kernel: 128x256 CTA, 64x32 warp tiles ----------------
__global__ __launch_bounds__(THREADS, 1)
void conv_stft_hmma_kernel(float* __restrict__ out)
{
    extern __shared__ char smem[];
    const uint32_t sbase = smem_u32(smem);
    const int tid  = threadIdx.x;
    const int wid  = tid >> 5;
    const int lane = tid & 31;

    const int c0 = blockIdx.x * TILE_M;
    const int f0 = blockIdx.y * TILE_N;
    const int b  = blockIdx.z;

    const char* wh_base = reinterpret_cast<const char*>(g_wh) + (size_t)c0 * KREAL * 2;
    const char* wl_base = reinterpret_cast<const char*>(g_wl) + (size_t)c0 * KREAL * 2;
    const char* xh_base = reinterpret_cast<const char*>(g_xh + (size_t)b * XPAD + f0 * HOP);
    const char* xl_base = reinterpret_cast<const char*>(g_xl + (size_t)b * XPAD + f0 * HOP);

    // coalesced staging: i = tid, unit index fastest
    auto stage = [&](int kc, int s) {
        const int last = (kc == 6);
        const int sha = last ? 1 : 3;              // log2(16B units per A row)
        const int na  = 2 * TILE_M << sha;
        #pragma unroll 2
        for (int i = tid; i < na; i += THREADS) {
            int per = TILE_M << sha;
            int split = i >= per;
            int j = i - split * per;
            int r = j >> sha, u = j & ((1 << sha) - 1);
            const char* src = (split ? wl_base : wh_base) + r * (KREAL * 2) + kc * 128 + u * 16;
            cp16(sbase + OFF_A(s) + split * A_SPLIT + r * PITCH_B + u * 16, src);
        }
        const int shb = last ? 2 : 4;              // log2(8B units per B row)
        const int nb  = 2 * TILE_N << shb;
        #pragma unroll 4
        for (int i = tid; i < nb; i += THREADS) {
            int per = TILE_N << shb;
            int split = i >= per;
            int j = i - split * per;
            int f = j >> shb, u = j & ((1 << shb) - 1);
            const char* src = (split ? xl_base : xh_base) + f * (HOP * 2) + kc * 128 + u * 8;
            cp8(sbase + OFF_B(s) + split * B_SPLIT + f * PITCH_B + u * 8, src);
        }
        cp_commit();
    };

    // warp layout: 2 (M) x 8 (N); warp tile 64 (M) x 32 (N)
    const int m0 = (wid >> 3) * 64;
    const int n0 = (wid & 7) * 32;

    float acc[4][4][4];                            // [mi][ni][frag]
    #pragma unroll
    for (int i = 0; i < 4; i++)
        #pragma unroll
        for (int j = 0; j < 4; j++)
            #pragma unroll
            for (int q = 0; q < 4; q++) acc[i][j][q] = 0.0f;

    const uint32_t a_off = (m0 + (lane & 15)) * PITCH_B + (lane >> 4) * 16;
    const uint32_t b_off = (n0 + ((lane >> 4) << 3) + (lane & 7)) * PITCH_B + ((lane >> 3) & 1) * 16;

    stage(0, 0);

    for (int kc = 0; kc < NCHUNK; kc++) {
        const int s = kc & 1;
        if (kc < NCHUNK - 1) { stage(kc + 1, s ^ 1); cp_wait<1>(); }
        else                 { cp_wait<0>(); }
        __syncthreads();

        const uint32_t ah_base = sbase + OFF_A(s) + a_off;
        const uint32_t al_base = ah_base + A_SPLIT;
        const uint32_t bh_base = sbase + OFF_B(s) + b_off;
        const uint32_t bl_base = bh_base + B_SPLIT;
        const int nks = (kc == 6) ? 1 : 4;

        for (int ks = 0; ks < nks; ks++) {
            // B fragments for the whole 32-wide warp strip (live across mi loop)
            uint32_t bh[2][4], bl[2][4];
            #pragma unroll
            for (int np = 0; np < 2; np++) {
                ldsm_x4(bh[np][0], bh[np][1], bh[np][2], bh[np][3],
                        bh_base + np * 16 * PITCH_B + ks * 32);
                ldsm_x4(bl[np][0], bl[np][1], bl[np][2], bl[np][3],
                        bl_base + np * 16 * PITCH_B + ks * 32);
            }
            #pragma unroll
            for (int mi = 0; mi < 4; mi++) {
                uint32_t ah[4], al[4];
                ldsm_x4(ah[0], ah[1], ah[2], ah[3],
                        ah_base + mi * 16 * PITCH_B + ks * 32);
                ldsm_x4(al[0], al[1], al[2], al[3],
                        al_base + mi * 16 * PITCH_B + ks * 32);
                // term-outer order: accumulator dependency distance = 4
                #pragma unroll
                for (int ni = 0; ni < 4; ni++)
                    mma16816(acc[mi][ni], ah, &bh[ni >> 1][(ni & 1) * 2]);
                #pragma unroll
                for (int ni = 0; ni < 4; ni++)
                    mma16816(acc[mi][ni], ah, &bl[ni >> 1][(ni & 1) * 2]);
                #pragma unroll
                for (int ni = 0; ni < 4; ni++)
                    mma16816(acc[mi][ni], al, &bh[ni >> 1][(ni & 1) * 2]);
            }
        }
        if (kc < NCHUNK - 1) __syncthreads();
    }

    // ---- epilogue: registers -> smem transpose -> coalesced stores ----
    __syncthreads();
    float* epi = reinterpret_cast<float*>(smem);
    const int g = lane >> 2;
    const int t = lane & 3;
    #pragma unroll
    for (int mi = 0; mi < 4; mi++)
        #pragma unroll
        for (int ni = 0; ni < 4; ni++) {
            int col = n0 + ni * 8 + t * 2;
            #pragma unroll
            for (int half = 0; half < 2; half++) {
                int row = m0 + mi * 16 + half * 8 + g;
                epi[row * EPI_PITCH + col]     = acc[mi][ni][half * 2];
                epi[row * EPI_PITCH + col + 1] = acc[mi][ni][half * 2 + 1];
            }
        }
    __syncthreads();

    #pragma unroll 4
    for (int idx = tid; idx < TILE_M * TILE_N; idx += THREADS) {
        int row = idx >> 8;           // / TILE_N
        int col = idx & 255;
        int R = c0 + row;
        int c = R + (R >= 257);
        int f = f0 + col;
        if (f < F_OUT)
            out[((size_t)b * C_OUT + c) * F_OUT + f] = epi[row * EPI_PITCH + col];
    }
}

// ---------------- launcher ----------------
extern "C" void kernel_launch(void* const* d_in, const int* in_sizes, int n_in,
                              void* d_out, int out_size)
{
    const float* x = (const float*)d_in[0];
    const float* w = (const float*)d_in[1];
    float* out = (float*)d_out;

    prep_w_kernel<<<(MROWS * KREAL + 255) / 256, 256>>>(w);
    prep_x_kernel<<<(int)(((size_t)BATCH * XPAD + 255) / 256), 256>>>(x);

    cudaFuncSetAttribute(edge_ch_kernel,
                         cudaFuncAttributeMaxDynamicSharedMemorySize,
                         (ZSEG + WIN) * (int)sizeof(float));
    dim3 zgrid((F_OUT + EFRM - 1) / EFRM, 2, BATCH);   // 19 x 2 x 32
    edge_ch_kernel<<<zgrid, EFRM, (ZSEG + WIN) * sizeof(float)>>>(x, w, out);

    cudaFuncSetAttribute(conv_stft_hmma_kernel,
                         cudaFuncAttributeMaxDynamicSharedMemorySize, SMEM_TOTAL);
    dim3 grid(NT_C, NT_F, BATCH);   // 4 x 19 x 32 = 2432 CTAs
    conv_stft_hmma_kernel<<<grid, THREADS, SMEM_TOTAL>>>(out);
}

// round 11
// speedup vs baseline: 1.3724x; 1.0903x over previous
#include <cuda_runtime.h>
#include <cuda_bf16.h>
#include <cstdint>

// ---------------- problem constants ----------------
#define WIN     400
#define HOP     100
#define PADL    300
#define T_IN    480000
#define BATCH   32
#define C_OUT   514
#define F_OUT   4803

#define MROWS   512               // C_OUT minus zero-structure channels 257, 513
#define KREAL   400               // 6 chunks of 64 + 1 chunk of 16
#define NCHUNK  7
#define XPAD    486784

#define TILE_M  128
#define TILE_N  256
#define NT_C    4
#define NT_F    19
#define THREADS 256

// ---------------- device scratch ----------------
__device__ __nv_bfloat16 g_wh[MROWS * KREAL];
__device__ __nv_bfloat16 g_wl[MROWS * KREAL];
__device__ __nv_bfloat16 g_xh[BATCH * (size_t)XPAD];
__device__ __nv_bfloat16 g_xl[BATCH * (size_t)XPAD];

// ---------------- smem layout ----------------
// persistent x segment: (256-1)*100 + 400 = 25900 elems = 51800 B per split
#define SEG_VECS     3238                      // cp16 units (51808 B)
#define SEG_BYTES    51840
#define OFF_SXH      0
#define OFF_SXL      SEG_BYTES
#define PITCH_A      144                       // 64 bf16 + 16B pad (16B-aligned rows)
#define A_SPLIT      (TILE_M * PITCH_A)        // 18432
#define A_STAGE      (2 * A_SPLIT)             // 36864
#define OFF_AST(s)   (2 * SEG_BYTES + (s) * A_STAGE)
#define SMEM_TOTAL   (2 * SEG_BYTES + 3 * A_STAGE)   // 214272
#define EPI_PITCH    257

// ---------------- helpers ----------------
__device__ __forceinline__ uint32_t smem_u32(const void* p) {
    uint32_t a;
    asm("{ .reg .u64 t; cvta.to.shared.u64 t, %1; cvt.u32.u64 %0, t; }" : "=r"(a) : "l"(p));
    return a;
}
__device__ __forceinline__ void cp16(uint32_t dst, const void* src) {
    asm volatile("cp.async.cg.shared.global [%0], [%1], 16;" :: "r"(dst), "l"(src));
}
__device__ __forceinline__ void cp_commit() {
    asm volatile("cp.async.commit_group;" ::: "memory");
}
template <int N>
__device__ __forceinline__ void cp_wait() {
    asm volatile("cp.async.wait_group %0;" :: "n"(N) : "memory");
}
__device__ __forceinline__ void ldsm_x4(uint32_t& r0, uint32_t& r1, uint32_t& r2, uint32_t& r3,
                                        uint32_t addr) {
    asm volatile("ldmatrix.sync.aligned.m8n8.x4.shared.b16 {%0,%1,%2,%3}, [%4];"
                 : "=r"(r0), "=r"(r1), "=r"(r2), "=r"(r3) : "r"(addr));
}
__device__ __forceinline__ void lds32(uint32_t& r, uint32_t addr) {
    asm volatile("ld.shared.b32 %0, [%1];" : "=r"(r) : "r"(addr));
}
__device__ __forceinline__ void mma16816(float* d, const uint32_t* a, const uint32_t* b) {
    asm volatile(
        "mma.sync.aligned.m16n8k16.row.col.f32.bf16.bf16.f32 "
        "{%0,%1,%2,%3}, {%4,%5,%6,%7}, {%8,%9}, {%0,%1,%2,%3};"
        : "+f"(d[0]), "+f"(d[1]), "+f"(d[2]), "+f"(d[3])
        : "r"(a[0]), "r"(a[1]), "r"(a[2]), "r"(a[3]), "r"(b[0]), "r"(b[1]));
}

// ---------------- prep kernels ----------------
// GEMM row r -> output channel c = r + (r >= 257)
__global__ void prep_w_kernel(const float* __restrict__ w) {
    int idx = blockIdx.x * blockDim.x + threadIdx.x;
    if (idx >= MROWS * KREAL) return;
    int r = idx / KREAL;
    int k = idx - r * KREAL;
    int c = r + (r >= 257);
    float v = w[c * KREAL + k];
    __nv_bfloat16 h = __float2bfloat16(v);
    g_wh[idx] = h;
    g_wl[idx] = __float2bfloat16(v - __bfloat162float(h));
}

__global__ void prep_x_kernel(const float* __restrict__ x) {
    size_t idx = (size_t)blockIdx.x * blockDim.x + threadIdx.x;
    if (idx >= (size_t)BATCH * XPAD) return;
    int b = (int)(idx / XPAD);
    int i = (int)(idx - (size_t)b * XPAD);
    int src = i - PADL;
    float v = (src >= 0 && src < T_IN) ? x[(size_t)b * T_IN + src] : 0.0f;
    __nv_bfloat16 h = __float2bfloat16(v);
    g_xh[idx] = h;
    g_xl[idx] = __float2bfloat16(v - __bfloat162float(h));
}

// ---------------- exact scalar conv for channels 257, 513 ----------------
#define EFRM 256
#define ZSEG ((EFRM - 1) * HOP + WIN)          // 25900 floats
__global__ void edge_ch_kernel(const float* __restrict__ x,
                               const float* __restrict__ w,
                               float* __restrict__ out)
{
    extern __shared__ float zs[];
    float* sxs = zs;
    float* sws = zs + ZSEG;
    const int f0 = blockIdx.x * EFRM;
    const int ch = (blockIdx.y == 0) ? 257 : 513;
    const int b  = blockIdx.z;
    const int tid = threadIdx.x;

    const int base = f0 * HOP - PADL;
    const float* xb = x + (size_t)b * T_IN;
    for (int i = tid; i < ZSEG; i += EFRM) {
        int gi = base + i;
        sxs[i] = (gi >= 0 && gi < T_IN) ? xb[gi] : 0.0f;
    }
    for (int i = tid; i < WIN; i += EFRM) sws[i] = w[ch * WIN + i];
    __syncthreads();

    float acc = 0.0f;
    const float* sp = sxs + tid * HOP;
    #pragma unroll 8
    for (int k = 0; k < WIN; k++) acc = fmaf(sp[k], sws[k], acc);

    int f = f0 + tid;
    if (f < F_OUT) out[((size_t)b * C_OUT + ch) * F_OUT + f] = acc;
}

// ---------------- main HMMA GEMM: persistent B (scalar frags), 64x64 warp tiles ----------------
__global__ __launch_bounds__(THREADS, 1)
void conv_stft_hmma_kernel(float* __restrict__ out)
{
    extern __shared__ char smem[];
    const uint32_t sbase = smem_u32(smem);
    const int tid  = threadIdx.x;
    const int wid  = tid >> 5;
    const int lane = tid & 31;

    const int c0 = blockIdx.x * TILE_M;
    const int f0 = blockIdx.y * TILE_N;
    const int b  = blockIdx.z;

    const char* wh_base = reinterpret_cast<const char*>(g_wh) + (size_t)c0 * (KREAL * 2);
    const char* wl_base = reinterpret_cast<const char*>(g_wl) + (size_t)c0 * (KREAL * 2);
    const char* xh_base = reinterpret_cast<const char*>(g_xh + (size_t)b * XPAD + f0 * HOP);
    const char* xl_base = reinterpret_cast<const char*>(g_xl + (size_t)b * XPAD + f0 * HOP);

    // ---- A chunk staging (coalesced, i = tid, unit fastest) ----
    auto stage_a = [&](int kc, int s) {
        const int sha = (kc == 6) ? 1 : 3;     // log2(16B units per row)
        const int na  = 2 * TILE_M << sha;
        #pragma unroll 2
        for (int i = tid; i < na; i += THREADS) {
            int per = TILE_M << sha;
            int split = i >= per;
            int j = i - split * per;
            int r = j >> sha, u = j & ((1 << sha) - 1);
            const char* src = (split ? wl_base : wh_base) + r * (KREAL * 2) + kc * 128 + u * 16;
            cp16(sbase + OFF_AST(s) + split * A_SPLIT + r * PITCH_A + u * 16, src);
        }
        cp_commit();
    };

    // ---- prologue: persistent x segment (both splits) + first two A chunks ----
    #pragma unroll 4
    for (int i = tid; i < 2 * SEG_VECS; i += THREADS) {
        int split = i >= SEG_VECS;
        int j = i - split * SEG_VECS;
        const char* src = (split ? xl_base : xh_base) + j * 16;
        cp16(sbase + (split ? OFF_SXL : OFF_SXH) + j * 16, src);
    }
    stage_a(0, 0);     // group 0 (includes segment copies)
    stage_a(1, 1);     // group 1

    // warp layout: 2 (M) x 4 (N); warp tile 64 x 64
    const int m0 = (wid >> 2) * 64;
    const int n0 = (wid & 3) * 64;

    float acc[4][8][4];
    #pragma unroll
    for (int i = 0; i < 4; i++)
        #pragma unroll
        for (int j = 0; j < 8; j++)
            #pragma unroll
            for (int q = 0; q < 4; q++) acc[i][j][q] = 0.0f;

    // per-lane offsets
    const uint32_t a_off = (m0 + (lane & 15)) * PITCH_A + (lane >> 4) * 16;
    // B fragment (m16n8k16): col n = lane/4, rows k = 2*(lane%4) (+1) and +8
    // element = x_seg[frame*100 + k] -> byte = frame*200 + k*2 (4B aligned, k even)
    const uint32_t bfrag0 = sbase + (uint32_t)((n0 + (lane >> 2)) * 200 + (lane & 3) * 4);

    for (int kc = 0; kc < NCHUNK; kc++) {
        const int s = kc % 3;
        if (kc < NCHUNK - 1) cp_wait<1>(); else cp_wait<0>();
        __syncthreads();                       // stage kc visible; buf (kc+2)%3 free
        if (kc + 2 < NCHUNK) stage_a(kc + 2, (kc + 2) % 3);

        const uint32_t ah_base = sbase + OFF_AST(s) + a_off;
        const uint32_t al_base = ah_base + A_SPLIT;
        const uint32_t bb_kc   = bfrag0 + kc * 128;       // +64 elems per chunk
        const int nks = (kc == 6) ? 1 : 4;

        for (int ks = 0; ks < nks; ks++) {
            // B fragments for the 64-wide strip: 8 n8-tiles x 2 regs, h and l
            uint32_t bh[8][2], bl[8][2];
            const uint32_t bb = bb_kc + ks * 32;          // +16 elems per k-step
            #pragma unroll
            for (int ni = 0; ni < 8; ni++) {
                uint32_t o = bb + ni * 1600;              // +8 frames per n8 tile
                lds32(bh[ni][0], o);
                lds32(bh[ni][1], o + 16);                 // k + 8
                lds32(bl[ni][0], o + SEG_BYTES);
                lds32(bl[ni][1], o + SEG_BYTES + 16);
            }
            #pragma unroll
            for (int mi = 0; mi < 4; mi++) {
                uint32_t ah[4], al[4];
                ldsm_x4(ah[0], ah[1], ah[2], ah[3],
                        ah_base + mi * 16 * PITCH_A + ks * 32);
                ldsm_x4(al[0], al[1], al[2], al[3],
                        al_base + mi * 16 * PITCH_A + ks * 32);
                #pragma unroll
                for (int ni = 0; ni < 8; ni++)
                    mma16816(acc[mi][ni], ah, bh[ni]);
                #pragma unroll
                for (int ni = 0; ni < 8; ni++)
                    mma16816(acc[mi][ni], ah, bl[ni]);
                #pragma unroll
                for (int ni = 0; ni < 8; ni++)
                    mma16816(acc[mi][ni], al, bh[ni]);
            }
        }
    }

    // ---- epilogue: registers -> smem transpose -> coalesced stores ----
    __syncthreads();
    float* epi = reinterpret_cast<float*>(smem);
    const int g = lane >> 2;
    const int t = lane & 3;
    #pragma unroll
    for (int mi = 0; mi < 4; mi++)
        #pragma unroll
        for (int ni = 0; ni < 8; ni++) {
            int col = n0 + ni * 8 + t * 2;
            #pragma unroll
            for (int half = 0; half < 2; half++) {
                int row = m0 + mi * 16 + half * 8 + g;
                epi[row * EPI_PITCH + col]     = acc[mi][ni][half * 2];
                epi[row * EPI_PITCH + col + 1] = acc[mi][ni][half * 2 + 1];
            }
        }
    __syncthreads();

    #pragma unroll 4
    for (int idx = tid; idx < TILE_M * TILE_N; idx += THREADS) {
        int row = idx >> 8;
        int col = idx & 255;
        int R = c0 + row;
        int c = R + (R >= 257);
        int f = f0 + col;
        if (f < F_OUT)
            out[((size_t)b * C_OUT + c) * F_OUT + f] = epi[row * EPI_PITCH + col];
    }
}

// ---------------- launcher ----------------
extern "C" void kernel_launch(void* const* d_in, const int* in_sizes, int n_in,
                              void* d_out, int out_size)
{
    const float* x = (const float*)d_in[0];
    const float* w = (const float*)d_in[1];
    float* out = (float*)d_out;

    prep_w_kernel<<<(MROWS * KREAL + 255) / 256, 256>>>(w);
    prep_x_kernel<<<(int)(((size_t)BATCH * XPAD + 255) / 256), 256>>>(x);

    cudaFuncSetAttribute(edge_ch_kernel,
                         cudaFuncAttributeMaxDynamicSharedMemorySize,
                         (ZSEG + WIN) * (int)sizeof(float));
    dim3 zgrid((F_OUT + EFRM - 1) / EFRM, 2, BATCH);   // 19 x 2 x 32
    edge_ch_kernel<<<zgrid, EFRM, (ZSEG + WIN) * sizeof(float)>>>(x, w, out);

    cudaFuncSetAttribute(conv_stft_hmma_kernel,
                         cudaFuncAttributeMaxDynamicSharedMemorySize, SMEM_TOTAL);
    dim3 grid(NT_C, NT_F, BATCH);   // 4 x 19 x 32 = 2432 CTAs
    conv_stft_hmma_kernel<<<grid, THREADS, SMEM_TOTAL>>>(out);
}

// round 12
// speedup vs baseline: 1.7085x; 1.2449x over previous
#include <cuda_runtime.h>
#include <cuda_fp16.h>
#include <cstdint>

// ---------------- problem constants ----------------
#define WIN     400
#define HOP     100
#define PADL    300
#define T_IN    480000
#define BATCH   32
#define C_OUT   514
#define F_OUT   4803

#define MROWS   512               // C_OUT minus zero-structure channels 257, 513
#define KREAL   400               // 6 chunks of 64 + 1 chunk of 16
#define NCHUNK  7
#define XPAD    486784

#define TILE_M  128
#define TILE_N  256
#define NT_C    4
#define NT_F    19
#define THREADS 256

// ---------------- device scratch ----------------
__device__ __half g_wh[MROWS * KREAL];
__device__ __half g_wl[MROWS * KREAL];
__device__ __half g_xh[BATCH * (size_t)XPAD];

// ---------------- smem layout ----------------
// persistent x segment: (256-1)*100 + 400 = 25900 elems = 51800 B (single fp16 split)
#define SEG_VECS     3238                      // cp16 units (51808 B)
#define SEG_BYTES    51840
#define OFF_SX       0
#define PITCH_A      144                       // 64 fp16 + 16B pad (16B-aligned rows)
#define A_SPLIT      (TILE_M * PITCH_A)        // 18432
#define A_STAGE      (2 * A_SPLIT)             // wh + wl = 36864
#define OFF_AST(s)   (SEG_BYTES + (s) * A_STAGE)
#define SMEM_TOTAL   (SEG_BYTES + 3 * A_STAGE) // 162432
#define EPI_PITCH    257

// ---------------- helpers ----------------
__device__ __forceinline__ uint32_t smem_u32(const void* p) {
    uint32_t a;
    asm("{ .reg .u64 t; cvta.to.shared.u64 t, %1; cvt.u32.u64 %0, t; }" : "=r"(a) : "l"(p));
    return a;
}
__device__ __forceinline__ void cp16(uint32_t dst, const void* src) {
    asm volatile("cp.async.cg.shared.global [%0], [%1], 16;" :: "r"(dst), "l"(src));
}
__device__ __forceinline__ void cp_commit() {
    asm volatile("cp.async.commit_group;" ::: "memory");
}
template <int N>
__device__ __forceinline__ void cp_wait() {
    asm volatile("cp.async.wait_group %0;" :: "n"(N) : "memory");
}
__device__ __forceinline__ void ldsm_x4(uint32_t& r0, uint32_t& r1, uint32_t& r2, uint32_t& r3,
                                        uint32_t addr) {
    asm volatile("ldmatrix.sync.aligned.m8n8.x4.shared.b16 {%0,%1,%2,%3}, [%4];"
                 : "=r"(r0), "=r"(r1), "=r"(r2), "=r"(r3) : "r"(addr));
}
__device__ __forceinline__ void lds32(uint32_t& r, uint32_t addr) {
    asm volatile("ld.shared.b32 %0, [%1];" : "=r"(r) : "r"(addr));
}
__device__ __forceinline__ void mma16816(float* d, const uint32_t* a, const uint32_t* b) {
    asm volatile(
        "mma.sync.aligned.m16n8k16.row.col.f32.f16.f16.f32 "
        "{%0,%1,%2,%3}, {%4,%5,%6,%7}, {%8,%9}, {%0,%1,%2,%3};"
        : "+f"(d[0]), "+f"(d[1]), "+f"(d[2]), "+f"(d[3])
        : "r"(a[0]), "r"(a[1]), "r"(a[2]), "r"(a[3]), "r"(b[0]), "r"(b[1]));
}

// ---------------- prep kernels ----------------
// GEMM row r -> output channel c = r + (r >= 257)
__global__ void prep_w_kernel(const float* __restrict__ w) {
    int idx = blockIdx.x * blockDim.x + threadIdx.x;
    if (idx >= MROWS * KREAL) return;
    int r = idx / KREAL;
    int k = idx - r * KREAL;
    int c = r + (r >= 257);
    float v = w[c * KREAL + k];
    __half h = __float2half(v);
    g_wh[idx] = h;
    g_wl[idx] = __float2half(v - __half2float(h));
}

__global__ void prep_x_kernel(const float* __restrict__ x) {
    size_t idx = (size_t)blockIdx.x * blockDim.x + threadIdx.x;
    if (idx >= (size_t)BATCH * XPAD) return;
    int b = (int)(idx / XPAD);
    int i = (int)(idx - (size_t)b * XPAD);
    int src = i - PADL;
    float v = (src >= 0 && src < T_IN) ? x[(size_t)b * T_IN + src] : 0.0f;
    g_xh[idx] = __float2half(v);
}

// ---------------- exact scalar conv for channels 257, 513 ----------------
#define EFRM 256
#define ZSEG ((EFRM - 1) * HOP + WIN)          // 25900 floats
__global__ void edge_ch_kernel(const float* __restrict__ x,
                               const float* __restrict__ w,
                               float* __restrict__ out)
{
    extern __shared__ float zs[];
    float* sxs = zs;
    float* sws = zs + ZSEG;
    const int f0 = blockIdx.x * EFRM;
    const int ch = (blockIdx.y == 0) ? 257 : 513;
    const int b  = blockIdx.z;
    const int tid = threadIdx.x;

    const int base = f0 * HOP - PADL;
    const float* xb = x + (size_t)b * T_IN;
    for (int i = tid; i < ZSEG; i += EFRM) {
        int gi = base + i;
        sxs[i] = (gi >= 0 && gi < T_IN) ? xb[gi] : 0.0f;
    }
    for (int i = tid; i < WIN; i += EFRM) sws[i] = w[ch * WIN + i];
    __syncthreads();

    float acc = 0.0f;
    const float* sp = sxs + tid * HOP;
    #pragma unroll 8
    for (int k = 0; k < WIN; k++) acc = fmaf(sp[k], sws[k], acc);

    int f = f0 + tid;
    if (f < F_OUT) out[((size_t)b * C_OUT + ch) * F_OUT + f] = acc;
}

// ---------------- main HMMA GEMM: fp16 2-term, persistent B, 64x64 warp tiles ----------------
__global__ __launch_bounds__(THREADS, 1)
void conv_stft_hmma_kernel(float* __restrict__ out)
{
    extern __shared__ char smem[];
    const uint32_t sbase = smem_u32(smem);
    const int tid  = threadIdx.x;
    const int wid  = tid >> 5;
    const int lane = tid & 31;

    const int c0 = blockIdx.x * TILE_M;
    const int f0 = blockIdx.y * TILE_N;
    const int b  = blockIdx.z;

    const char* wh_base = reinterpret_cast<const char*>(g_wh) + (size_t)c0 * (KREAL * 2);
    const char* wl_base = reinterpret_cast<const char*>(g_wl) + (size_t)c0 * (KREAL * 2);
    const char* xh_base = reinterpret_cast<const char*>(g_xh + (size_t)b * XPAD + f0 * HOP);

    // ---- A chunk staging (coalesced, i = tid, unit fastest); both w splits ----
    auto stage_a = [&](int kc, int s) {
        const int sha = (kc == 6) ? 1 : 3;     // log2(16B units per row)
        const int na  = 2 * TILE_M << sha;
        #pragma unroll 2
        for (int i = tid; i < na; i += THREADS) {
            int per = TILE_M << sha;
            int split = i >= per;
            int j = i - split * per;
            int r = j >> sha, u = j & ((1 << sha) - 1);
            const char* src = (split ? wl_base : wh_base) + r * (KREAL * 2) + kc * 128 + u * 16;
            cp16(sbase + OFF_AST(s) + split * A_SPLIT + r * PITCH_A + u * 16, src);
        }
        cp_commit();
    };

    // ---- prologue: persistent x segment + first two A chunks ----
    #pragma unroll 4
    for (int i = tid; i < SEG_VECS; i += THREADS)
        cp16(sbase + OFF_SX + i * 16, xh_base + i * 16);
    stage_a(0, 0);     // group 0 (includes segment copies)
    stage_a(1, 1);     // group 1

    // warp layout: 2 (M) x 4 (N); warp tile 64 x 64
    const int m0 = (wid >> 2) * 64;
    const int n0 = (wid & 3) * 64;

    float acc[4][8][4];
    #pragma unroll
    for (int i = 0; i < 4; i++)
        #pragma unroll
        for (int j = 0; j < 8; j++)
            #pragma unroll
            for (int q = 0; q < 4; q++) acc[i][j][q] = 0.0f;

    // per-lane offsets
    const uint32_t a_off = (m0 + (lane & 15)) * PITCH_A + (lane >> 4) * 16;
    // B fragment (m16n8k16): col n = lane/4, rows k = 2*(lane%4) (+1) and +8
    // element = x_seg[frame*100 + k] -> byte = frame*200 + k*2 (4B aligned)
    const uint32_t bfrag0 = sbase + (uint32_t)((n0 + (lane >> 2)) * 200 + (lane & 3) * 4);

    for (int kc = 0; kc < NCHUNK; kc++) {
        const int s = kc % 3;
        if (kc < NCHUNK - 1) cp_wait<1>(); else cp_wait<0>();
        __syncthreads();                       // stage kc visible; buf (kc+2)%3 free
        if (kc + 2 < NCHUNK) stage_a(kc + 2, (kc + 2) % 3);

        const uint32_t ah_base = sbase + OFF_AST(s) + a_off;
        const uint32_t al_base = ah_base + A_SPLIT;
        const uint32_t bb_kc   = bfrag0 + kc * 128;       // +64 elems per chunk
        const int nks = (kc == 6) ? 1 : 4;

        for (int ks = 0; ks < nks; ks++) {
            // B fragments for the 64-wide strip: 8 n8-tiles x 2 regs (x_h only)
            uint32_t bh[8][2];
            const uint32_t bb = bb_kc + ks * 32;          // +16 elems per k-step
            #pragma unroll
            for (int ni = 0; ni < 8; ni++) {
                uint32_t o = bb + ni * 1600;              // +8 frames per n8 tile
                lds32(bh[ni][0], o);
                lds32(bh[ni][1], o + 16);                 // k + 8
            }
            #pragma unroll
            for (int mi = 0; mi < 4; mi++) {
                uint32_t ah[4], al[4];
                ldsm_x4(ah[0], ah[1], ah[2], ah[3],
                        ah_base + mi * 16 * PITCH_A + ks * 32);
                ldsm_x4(al[0], al[1], al[2], al[3],
                        al_base + mi * 16 * PITCH_A + ks * 32);
                #pragma unroll
                for (int ni = 0; ni < 8; ni++)
                    mma16816(acc[mi][ni], ah, bh[ni]);    // w_h * x_h
                #pragma unroll
                for (int ni = 0; ni < 8; ni++)
                    mma16816(acc[mi][ni], al, bh[ni]);    // w_l * x_h
            }
        }
    }

    // ---- epilogue: registers -> smem transpose -> coalesced stores ----
    __syncthreads();
    float* epi = reinterpret_cast<float*>(smem);
    const int g = lane >> 2;
    const int t = lane & 3;
    #pragma unroll
    for (int mi = 0; mi < 4; mi++)
        #pragma unroll
        for (int ni = 0; ni < 8; ni++) {
            int col = n0 + ni * 8 + t * 2;
            #pragma unroll
            for (int half = 0; half < 2; half++) {
                int row = m0 + mi * 16 + half * 8 + g;
                epi[row * EPI_PITCH + col]     = acc[mi][ni][half * 2];
                epi[row * EPI_PITCH + col + 1] = acc[mi][ni][half * 2 + 1];
            }
        }
    __syncthreads();

    #pragma unroll 4
    for (int idx = tid; idx < TILE_M * TILE_N; idx += THREADS) {
        int row = idx >> 8;
        int col = idx & 255;
        int R = c0 + row;
        int c = R + (R >= 257);
        int f = f0 + col;
        if (f < F_OUT)
            out[((size_t)b * C_OUT + c) * F_OUT + f] = epi[row * EPI_PITCH + col];
    }
}

// ---------------- launcher ----------------
extern "C" void kernel_launch(void* const* d_in, const int* in_sizes, int n_in,
                              void* d_out, int out_size)
{
    const float* x = (const float*)d_in[0];
    const float* w = (const float*)d_in[1];
    float* out = (float*)d_out;

    prep_w_kernel<<<(MROWS * KREAL + 255) / 256, 256>>>(w);
    prep_x_kernel<<<(int)(((size_t)BATCH * XPAD + 255) / 256), 256>>>(x);

    cudaFuncSetAttribute(edge_ch_kernel,
                         cudaFuncAttributeMaxDynamicSharedMemorySize,
                         (ZSEG + WIN) * (int)sizeof(float));
    dim3 zgrid((F_OUT + EFRM - 1) / EFRM, 2, BATCH);   // 19 x 2 x 32
    edge_ch_kernel<<<zgrid, EFRM, (ZSEG + WIN) * sizeof(float)>>>(x, w, out);

    cudaFuncSetAttribute(conv_stft_hmma_kernel,
                         cudaFuncAttributeMaxDynamicSharedMemorySize, SMEM_TOTAL);
    dim3 grid(NT_C, NT_F, BATCH);   // 4 x 19 x 32 = 2432 CTAs
    conv_stft_hmma_kernel<<<grid, THREADS, SMEM_TOTAL>>>(out);
}

// round 13
// speedup vs baseline: 1.7525x; 1.0258x over previous
#include <cuda_runtime.h>
#include <cuda_fp16.h>
#include <cstdint>

// ---------------- problem constants ----------------
#define WIN     400
#define HOP     100
#define PADL    300
#define T_IN    480000
#define BATCH   32
#define C_OUT   514
#define F_OUT   4803

#define MROWS   512               // C_OUT minus zero-structure channels 257, 513
#define KREAL   400               // 5 uniform chunks of 80
#define KCH     80
#define NCHUNK  5
#define XPAD    486784

#define TILE_M  128
#define TILE_N  256
#define NT_C    4
#define NT_F    19
#define THREADS 256

// ---------------- device scratch ----------------
__device__ __half g_wh[MROWS * KREAL];
__device__ __half g_wl[MROWS * KREAL];
__device__ __half g_xh[BATCH * (size_t)XPAD];

// ---------------- smem layout ----------------
// persistent x segment: (256-1)*100 + 400 = 25900 elems = 51800 B (fp16)
#define SEG_VECS     3238                      // cp16 units (51808 B)
#define SEG_BYTES    51840
#define OFF_SX       0
#define PITCH_A      176                       // 80 fp16 (160B) + 16B pad; rows 16B-aligned
#define A_SPLIT      (TILE_M * PITCH_A)        // 22528
#define A_STAGE      (2 * A_SPLIT)             // wh + wl = 45056
#define OFF_AST(s)   (SEG_BYTES + (s) * A_STAGE)
#define SMEM_TOTAL   (SEG_BYTES + 3 * A_STAGE) // 187008
#define EPI_PITCH    257

// ---------------- helpers ----------------
__device__ __forceinline__ uint32_t smem_u32(const void* p) {
    uint32_t a;
    asm("{ .reg .u64 t; cvta.to.shared.u64 t, %1; cvt.u32.u64 %0, t; }" : "=r"(a) : "l"(p));
    return a;
}
__device__ __forceinline__ void cp16(uint32_t dst, const void* src) {
    asm volatile("cp.async.cg.shared.global [%0], [%1], 16;" :: "r"(dst), "l"(src));
}
__device__ __forceinline__ void cp_commit() {
    asm volatile("cp.async.commit_group;" ::: "memory");
}
template <int N>
__device__ __forceinline__ void cp_wait() {
    asm volatile("cp.async.wait_group %0;" :: "n"(N) : "memory");
}
__device__ __forceinline__ void ldsm_x4(uint32_t& r0, uint32_t& r1, uint32_t& r2, uint32_t& r3,
                                        uint32_t addr) {
    asm volatile("ldmatrix.sync.aligned.m8n8.x4.shared.b16 {%0,%1,%2,%3}, [%4];"
                 : "=r"(r0), "=r"(r1), "=r"(r2), "=r"(r3) : "r"(addr));
}
__device__ __forceinline__ void lds32(uint32_t& r, uint32_t addr) {
    asm volatile("ld.shared.b32 %0, [%1];" : "=r"(r) : "r"(addr));
}
__device__ __forceinline__ void mma16816(float* d, const uint32_t* a, const uint32_t* b) {
    asm volatile(
        "mma.sync.aligned.m16n8k16.row.col.f32.f16.f16.f32 "
        "{%0,%1,%2,%3}, {%4,%5,%6,%7}, {%8,%9}, {%0,%1,%2,%3};"
        : "+f"(d[0]), "+f"(d[1]), "+f"(d[2]), "+f"(d[3])
        : "r"(a[0]), "r"(a[1]), "r"(a[2]), "r"(a[3]), "r"(b[0]), "r"(b[1]));
}

// ---------------- prep kernels ----------------
// GEMM row r -> output channel c = r + (r >= 257)
__global__ void prep_w_kernel(const float* __restrict__ w) {
    int idx = blockIdx.x * blockDim.x + threadIdx.x;
    if (idx >= MROWS * KREAL) return;
    int r = idx / KREAL;
    int k = idx - r * KREAL;
    int c = r + (r >= 257);
    float v = w[c * KREAL + k];
    __half h = __float2half(v);
    g_wh[idx] = h;
    g_wl[idx] = __float2half(v - __half2float(h));
}

__global__ void prep_x_kernel(const float* __restrict__ x) {
    size_t idx = (size_t)blockIdx.x * blockDim.x + threadIdx.x;
    if (idx >= (size_t)BATCH * XPAD) return;
    int b = (int)(idx / XPAD);
    int i = (int)(idx - (size_t)b * XPAD);
    int src = i - PADL;
    float v = (src >= 0 && src < T_IN) ? x[(size_t)b * T_IN + src] : 0.0f;
    g_xh[idx] = __float2half(v);
}

// ---------------- exact scalar conv for channels 257, 513 ----------------
#define EFRM 256
#define ZSEG ((EFRM - 1) * HOP + WIN)          // 25900 floats
__global__ void edge_ch_kernel(const float* __restrict__ x,
                               const float* __restrict__ w,
                               float* __restrict__ out)
{
    extern __shared__ float zs[];
    float* sxs = zs;
    float* sws = zs + ZSEG;
    const int f0 = blockIdx.x * EFRM;
    const int ch = (blockIdx.y == 0) ? 257 : 513;
    const int b  = blockIdx.z;
    const int tid = threadIdx.x;

    const int base = f0 * HOP - PADL;
    const float* xb = x + (size_t)b * T_IN;
    for (int i = tid; i < ZSEG; i += EFRM) {
        int gi = base + i;
        sxs[i] = (gi >= 0 && gi < T_IN) ? xb[gi] : 0.0f;
    }
    for (int i = tid; i < WIN; i += EFRM) sws[i] = w[ch * WIN + i];
    __syncthreads();

    float acc = 0.0f;
    const float* sp = sxs + tid * HOP;
    #pragma unroll 8
    for (int k = 0; k < WIN; k++) acc = fmaf(sp[k], sws[k], acc);

    int f = f0 + tid;
    if (f < F_OUT) out[((size_t)b * C_OUT + ch) * F_OUT + f] = acc;
}

// ---------------- main HMMA GEMM: fp16 2-term, persistent B, 64x64 warp tiles ----------------
__global__ __launch_bounds__(THREADS, 1)
void conv_stft_hmma_kernel(float* __restrict__ out)
{
    extern __shared__ char smem[];
    const uint32_t sbase = smem_u32(smem);
    const int tid  = threadIdx.x;
    const int wid  = tid >> 5;
    const int lane = tid & 31;

    const int c0 = blockIdx.x * TILE_M;
    const int f0 = blockIdx.y * TILE_N;
    const int b  = blockIdx.z;

    const char* wh_base = reinterpret_cast<const char*>(g_wh) + (size_t)c0 * (KREAL * 2);
    const char* wl_base = reinterpret_cast<const char*>(g_wl) + (size_t)c0 * (KREAL * 2);
    const char* xh_base = reinterpret_cast<const char*>(g_xh + (size_t)b * XPAD + f0 * HOP);

    // ---- A chunk staging: 80 fp16 (10x16B) per row, both w splits ----
    auto stage_a = [&](int kc, int s) {
        #pragma unroll 2
        for (int i = tid; i < 2 * TILE_M * 10; i += THREADS) {
            int per = TILE_M * 10;
            int split = i >= per;
            int j = i - split * per;
            int r = j / 10, u = j - r * 10;
            const char* src = (split ? wl_base : wh_base) + r * (KREAL * 2) + kc * 160 + u * 16;
            cp16(sbase + OFF_AST(s) + split * A_SPLIT + r * PITCH_A + u * 16, src);
        }
        cp_commit();
    };

    // ---- prologue: persistent x segment + first two A chunks ----
    #pragma unroll 4
    for (int i = tid; i < SEG_VECS; i += THREADS)
        cp16(sbase + OFF_SX + i * 16, xh_base + i * 16);
    stage_a(0, 0);     // group 0 (includes segment copies)
    stage_a(1, 1);     // group 1

    // warp layout: 2 (M) x 4 (N); warp tile 64 x 64
    const int m0 = (wid >> 2) * 64;
    const int n0 = (wid & 3) * 64;

    float acc[4][8][4];
    #pragma unroll
    for (int i = 0; i < 4; i++)
        #pragma unroll
        for (int j = 0; j < 8; j++)
            #pragma unroll
            for (int q = 0; q < 4; q++) acc[i][j][q] = 0.0f;

    // per-lane offsets
    const uint32_t a_off = (m0 + (lane & 15)) * PITCH_A + (lane >> 4) * 16;
    // B fragment (m16n8k16): col n = lane/4, rows k = 2*(lane%4) (+1) and +8
    const uint32_t bfrag0 = sbase + (uint32_t)((n0 + (lane >> 2)) * 200 + (lane & 3) * 4);

    for (int kc = 0; kc < NCHUNK; kc++) {
        const int s = kc % 3;
        if (kc < NCHUNK - 1) cp_wait<1>(); else cp_wait<0>();
        __syncthreads();                       // stage kc visible; buf (kc+2)%3 free
        if (kc + 2 < NCHUNK) stage_a(kc + 2, (kc + 2) % 3);

        const uint32_t ah_base = sbase + OFF_AST(s) + a_off;
        const uint32_t al_base = ah_base + A_SPLIT;
        const uint32_t bb_kc   = bfrag0 + kc * 160;       // +80 elems per chunk

        #pragma unroll
        for (int ks = 0; ks < 5; ks++) {
            // B fragments for the 64-wide strip: 8 n8-tiles x 2 regs (x_h only)
            uint32_t bh[8][2];
            const uint32_t bb = bb_kc + ks * 32;          // +16 elems per k-step
            #pragma unroll
            for (int ni = 0; ni < 8; ni++) {
                uint32_t o = bb + ni * 1600;              // +8 frames per n8 tile
                lds32(bh[ni][0], o);
                lds32(bh[ni][1], o + 16);                 // k + 8
            }
            // A fragments double-buffered across mi: load mi+1 while mi's MMAs drain
            uint32_t ahf[2][4], alf[2][4];
            ldsm_x4(ahf[0][0], ahf[0][1], ahf[0][2], ahf[0][3], ah_base + ks * 32);
            ldsm_x4(alf[0][0], alf[0][1], alf[0][2], alf[0][3], al_base + ks * 32);
            #pragma unroll
            for (int mi = 0; mi < 4; mi++) {
                const int cur = mi & 1;
                if (mi < 3) {
                    ldsm_x4(ahf[cur ^ 1][0], ahf[cur ^ 1][1], ahf[cur ^ 1][2], ahf[cur ^ 1][3],
                            ah_base + (mi + 1) * 16 * PITCH_A + ks * 32);
                    ldsm_x4(alf[cur ^ 1][0], alf[cur ^ 1][1], alf[cur ^ 1][2], alf[cur ^ 1][3],
                            al_base + (mi + 1) * 16 * PITCH_A + ks * 32);
                }
                #pragma unroll
                for (int ni = 0; ni < 8; ni++)
                    mma16816(acc[mi][ni], ahf[cur], bh[ni]);    // w_h * x_h
                #pragma unroll
                for (int ni = 0; ni < 8; ni++)
                    mma16816(acc[mi][ni], alf[cur], bh[ni]);    // w_l * x_h
            }
        }
    }

    // ---- epilogue: registers -> smem transpose -> coalesced stores ----
    __syncthreads();
    float* epi = reinterpret_cast<float*>(smem);
    const int g = lane >> 2;
    const int t = lane & 3;
    #pragma unroll
    for (int mi = 0; mi < 4; mi++)
        #pragma unroll
        for (int ni = 0; ni < 8; ni++) {
            int col = n0 + ni * 8 + t * 2;
            #pragma unroll
            for (int half = 0; half < 2; half++) {
                int row = m0 + mi * 16 + half * 8 + g;
                epi[row * EPI_PITCH + col]     = acc[mi][ni][half * 2];
                epi[row * EPI_PITCH + col + 1] = acc[mi][ni][half * 2 + 1];
            }
        }
    __syncthreads();

    #pragma unroll 4
    for (int idx = tid; idx < TILE_M * TILE_N; idx += THREADS) {
        int row = idx >> 8;
        int col = idx & 255;
        int R = c0 + row;
        int c = R + (R >= 257);
        int f = f0 + col;
        if (f < F_OUT)
            out[((size_t)b * C_OUT + c) * F_OUT + f] = epi[row * EPI_PITCH + col];
    }
}

// ---------------- launcher ----------------
extern "C" void kernel_launch(void* const* d_in, const int* in_sizes, int n_in,
                              void* d_out, int out_size)
{
    const float* x = (const float*)d_in[0];
    const float* w = (const float*)d_in[1];
    float* out = (float*)d_out;

    prep_w_kernel<<<(MROWS * KREAL + 255) / 256, 256>>>(w);
    prep_x_kernel<<<(int)(((size_t)BATCH * XPAD + 255) / 256), 256>>>(x);

    cudaFuncSetAttribute(edge_ch_kernel,
                         cudaFuncAttributeMaxDynamicSharedMemorySize,
                         (ZSEG + WIN) * (int)sizeof(float));
    dim3 zgrid((F_OUT + EFRM - 1) / EFRM, 2, BATCH);   // 19 x 2 x 32
    edge_ch_kernel<<<zgrid, EFRM, (ZSEG + WIN) * sizeof(float)>>>(x, w, out);

    cudaFuncSetAttribute(conv_stft_hmma_kernel,
                         cudaFuncAttributeMaxDynamicSharedMemorySize, SMEM_TOTAL);
    dim3 grid(NT_C, NT_F, BATCH);   // 4 x 19 x 32 = 2432 CTAs
    conv_stft_hmma_kernel<<<grid, THREADS, SMEM_TOTAL>>>(out);
}